// round 12
// baseline (speedup 1.0000x reference)
#include <cuda_runtime.h>
#include <cuda_bf16.h>
#include <math.h>
#include <stdint.h>

#define Bsz 16384
#define Hd  128
#define Cc  4
#define Ll  6
#define NHh 4
#define HDd 32
#define Oo  1024
#define G3H 384

// ---------------- fp32 scratch ----------------------------------------------
__device__ __align__(256) float g_gi [(size_t)Cc * Bsz * G3H];   // permuted gi
__device__ __align__(256) float g_qkv[(size_t)Cc * Bsz * G3H];
__device__ __align__(256) float g_hn [(size_t)Cc * Bsz * Hd];
__device__ __align__(256) float g_msg[(size_t)Cc * Bsz * Hd];

// ---------------- bf16 hi/lo split buffers ----------------------------------
__device__ __align__(256) __nv_bfloat16 g_x0h[(size_t)Bsz * Hd];
__device__ __align__(256) __nv_bfloat16 g_x0l[(size_t)Bsz * Hd];
__device__ __align__(256) __nv_bfloat16 g_hh [(size_t)Ll * Cc * Bsz * Hd];  // h_in split
__device__ __align__(256) __nv_bfloat16 g_hl [(size_t)Ll * Cc * Bsz * Hd];
__device__ __align__(256) __nv_bfloat16 g_nh [(size_t)Cc * Bsz * Hd];       // hn split
__device__ __align__(256) __nv_bfloat16 g_nl [(size_t)Cc * Bsz * Hd];
__device__ __align__(256) __nv_bfloat16 g_aah[(size_t)Cc * Bsz * Hd];       // att split
__device__ __align__(256) __nv_bfloat16 g_aal[(size_t)Cc * Bsz * Hd];
__device__ __align__(256) __nv_bfloat16 g_ph [(size_t)Cc * Bsz * Hd];       // hOut split
__device__ __align__(256) __nv_bfloat16 g_pl [(size_t)Cc * Bsz * Hd];
// weights (gate weights stored PERMUTED: row p = gate p%3, hidden p/3)
__device__ __align__(256) __nv_bfloat16 g_wih0h[(size_t)G3H * Hd];
__device__ __align__(256) __nv_bfloat16 g_wih0l[(size_t)G3H * Hd];
__device__ __align__(256) __nv_bfloat16 g_whh0h[(size_t)Cc * G3H * Hd];
__device__ __align__(256) __nv_bfloat16 g_whh0l[(size_t)Cc * G3H * Hd];
__device__ __align__(256) __nv_bfloat16 g_wihh[(size_t)(Ll-1) * Cc * G3H * Hd];
__device__ __align__(256) __nv_bfloat16 g_wihl[(size_t)(Ll-1) * Cc * G3H * Hd];
__device__ __align__(256) __nv_bfloat16 g_whhh[(size_t)(Ll-1) * Cc * G3H * Hd];
__device__ __align__(256) __nv_bfloat16 g_whhl[(size_t)(Ll-1) * Cc * G3H * Hd];
__device__ __align__(256) __nv_bfloat16 g_aiwh[(size_t)Ll * G3H * Hd];
__device__ __align__(256) __nv_bfloat16 g_aiwl[(size_t)Ll * G3H * Hd];
__device__ __align__(256) __nv_bfloat16 g_aowh[(size_t)Ll * Hd * Hd];
__device__ __align__(256) __nv_bfloat16 g_aowl[(size_t)Ll * Hd * Hd];
__device__ __align__(256) __nv_bfloat16 g_hwh [(size_t)Oo * Hd];
__device__ __align__(256) __nv_bfloat16 g_hwl [(size_t)Oo * Hd];
// permuted fp32 gate biases
__device__ __align__(256) float g_bih0P[(size_t)Cc * G3H];
__device__ __align__(256) float g_bhh0P[(size_t)Cc * G3H];
__device__ __align__(256) float g_bihP [(size_t)(Ll-1) * Cc * G3H];
__device__ __align__(256) float g_bhhP [(size_t)(Ll-1) * Cc * G3H];

__device__ __forceinline__ float sigf(float x) { return 1.0f / (1.0f + expf(-x)); }

__device__ __forceinline__ uint32_t pack_bf16(__nv_bfloat16 a, __nv_bfloat16 b) {
    __nv_bfloat162 t = __nv_bfloat162(a, b);
    return *reinterpret_cast<uint32_t*>(&t);
}

__device__ __forceinline__ void store_split4(__nv_bfloat16* ph, __nv_bfloat16* pl,
                                             long off, float4 v) {
    __nv_bfloat16 h0 = __float2bfloat16(v.x);
    __nv_bfloat16 h1 = __float2bfloat16(v.y);
    __nv_bfloat16 h2 = __float2bfloat16(v.z);
    __nv_bfloat16 h3 = __float2bfloat16(v.w);
    *reinterpret_cast<uint2*>(ph + off) =
        make_uint2(pack_bf16(h0, h1), pack_bf16(h2, h3));
    __nv_bfloat16 l0 = __float2bfloat16(v.x - __bfloat162float(h0));
    __nv_bfloat16 l1 = __float2bfloat16(v.y - __bfloat162float(h1));
    __nv_bfloat16 l2 = __float2bfloat16(v.z - __bfloat162float(h2));
    __nv_bfloat16 l3 = __float2bfloat16(v.w - __bfloat162float(h3));
    *reinterpret_cast<uint2*>(pl + off) =
        make_uint2(pack_bf16(l0, l1), pack_bf16(l2, l3));
}

// ---------------- generic fp32 -> bf16 hi/lo split pass ---------------------
__global__ void split_pair(const float* __restrict__ in, __nv_bfloat16* __restrict__ oh,
                           __nv_bfloat16* __restrict__ ol)
{
    long i = (long)blockIdx.x * 256 + threadIdx.x;   // float4 index
    float4 v = reinterpret_cast<const float4*>(in)[i];
    store_split4(oh, ol, i * 4, v);
}

// ---------------- gate weight permute + split --------------------------------
// in: [M][384][128] fp32; out row p = in row (p%3)*128 + p/3  (within matrix)
__global__ void permute_split_w(const float* __restrict__ in,
                                __nv_bfloat16* __restrict__ oh,
                                __nv_bfloat16* __restrict__ ol)
{
    long i = (long)blockIdx.x * 256 + threadIdx.x;   // float4 units
    int  k4 = (int)(i & 31);
    long row = i >> 5;                               // m*384 + p
    int  p = (int)(row % 384);
    long m = row / 384;
    long src = (m * 384 + (long)(p % 3) * 128 + p / 3) * 128 + k4 * 4;
    float4 v = *(const float4*)(in + src);
    store_split4(oh, ol, row * 128 + (long)k4 * 4, v);
}

__global__ void permute_bias(const float* __restrict__ in, float* __restrict__ out, int total)
{
    int i = blockIdx.x * 256 + threadIdx.x;
    if (i >= total) return;
    int p = i % 384;
    int m = i / 384;
    out[i] = in[m * 384 + (p % 3) * 128 + p / 3];
}

// ======================= shared GEMM machinery =======================
#define KPAD    136
#define ROWB    (KPAD * 2)            // 272 bytes per row

__device__ __forceinline__ uint32_t smem_u32(const void* p) {
    uint32_t a;
    asm("{ .reg .u64 t; cvta.to.shared.u64 t, %1; cvt.u32.u64 %0, t; }" : "=r"(a) : "l"(p));
    return a;
}
__device__ __forceinline__ void cpa16(uint32_t sdst, const void* gsrc) {
    asm volatile("cp.async.cg.shared.global [%0], [%1], 16;" :: "r"(sdst), "l"(gsrc));
}
#define CP_COMMIT() asm volatile("cp.async.commit_group;" ::: "memory")
#define CP_WAIT(n)  asm volatile("cp.async.wait_group %0;" :: "n"(n) : "memory")

__device__ __forceinline__ void mma16816(float* c, const uint32_t* a, const uint32_t* b) {
    asm volatile(
        "mma.sync.aligned.m16n8k16.row.col.f32.bf16.bf16.f32 "
        "{%0,%1,%2,%3}, {%4,%5,%6,%7}, {%8,%9}, {%0,%1,%2,%3};\n"
        : "+f"(c[0]), "+f"(c[1]), "+f"(c[2]), "+f"(c[3])
        : "r"(a[0]), "r"(a[1]), "r"(a[2]), "r"(a[3]), "r"(b[0]), "r"(b[1]));
}

#define LDSM_X4(r0, r1, r2, r3, addr) \
    asm volatile("ldmatrix.sync.aligned.m8n8.x4.shared.b16 {%0,%1,%2,%3}, [%4];" \
                 : "=r"(r0), "=r"(r1), "=r"(r2), "=r"(r3) : "r"(addr))
#define LDSM_X2(r0, r1, addr) \
    asm volatile("ldmatrix.sync.aligned.m8n8.x2.shared.b16 {%0,%1}, [%2];" \
                 : "=r"(r0), "=r"(r1) : "r"(addr))

// ======================= plain GEMM (128x64, 2 CTA/SM) =======================
#define TILE_A  ((size_t)128 * ROWB)
#define TILE_Bt ((size_t)64  * ROWB)
#define SM_AH   0
#define SM_AL   (SM_AH + TILE_A)
#define SM_BH   (SM_AL + TILE_A)
#define SM_BL   (SM_BH + TILE_Bt)
#define SM_TOT  (SM_BL + TILE_Bt)     // 104448 bytes

struct Frags {
    uint32_t ah[2][4];
    uint32_t al[2][4];
    uint32_t bh[4][2];
    uint32_t bl[4][2];
};

__device__ __forceinline__ void ld_frags(Frags& f, uint32_t aH, uint32_t aL,
                                         uint32_t bH, uint32_t bL) {
    #pragma unroll
    for (int i = 0; i < 2; i++)
        LDSM_X4(f.ah[i][0], f.ah[i][1], f.ah[i][2], f.ah[i][3], aH + i * (16 * ROWB));
    #pragma unroll
    for (int i = 0; i < 2; i++)
        LDSM_X4(f.al[i][0], f.al[i][1], f.al[i][2], f.al[i][3], aL + i * (16 * ROWB));
    LDSM_X4(f.bh[0][0], f.bh[0][1], f.bh[1][0], f.bh[1][1], bH);
    LDSM_X4(f.bh[2][0], f.bh[2][1], f.bh[3][0], f.bh[3][1], bH + 16 * ROWB);
    LDSM_X4(f.bl[0][0], f.bl[0][1], f.bl[1][0], f.bl[1][1], bL);
    LDSM_X4(f.bl[2][0], f.bl[2][1], f.bl[3][0], f.bl[3][1], bL + 16 * ROWB);
}

__device__ __forceinline__ void mma_all(float acc[2][4][4], Frags& f) {
    #pragma unroll
    for (int i = 0; i < 2; i++)
        #pragma unroll
        for (int j = 0; j < 4; j++)
            mma16816(acc[i][j], f.ah[i], f.bh[j]);
    #pragma unroll
    for (int i = 0; i < 2; i++)
        #pragma unroll
        for (int j = 0; j < 4; j++)
            mma16816(acc[i][j], f.ah[i], f.bl[j]);
    #pragma unroll
    for (int i = 0; i < 2; i++)
        #pragma unroll
        for (int j = 0; j < 4; j++)
            mma16816(acc[i][j], f.al[i], f.bh[j]);
}

__device__ __forceinline__ void fill_half(
    uint32_t sb, int tid, int h,
    const __nv_bfloat16* a_h, const __nv_bfloat16* a_l,
    const __nv_bfloat16* b_h, const __nv_bfloat16* b_l)
{
    #pragma unroll 2
    for (int idx = tid; idx < 1024; idx += 256) {        // A: 128 rows x 8 chunks
        int r = idx >> 3, k = (idx & 7) + h * 8;
        cpa16(sb + SM_AH + r * ROWB + k * 16, a_h + (long)r * 128 + k * 8);
        cpa16(sb + SM_AL + r * ROWB + k * 16, a_l + (long)r * 128 + k * 8);
    }
    #pragma unroll 2
    for (int idx = tid; idx < 512; idx += 256) {         // B: 64 rows x 8 chunks
        int r = idx >> 3, k = (idx & 7) + h * 8;
        cpa16(sb + SM_BH + r * ROWB + k * 16, b_h + (long)r * 128 + k * 8);
        cpa16(sb + SM_BL + r * ROWB + k * 16, b_l + (long)r * 128 + k * 8);
    }
}

__device__ __forceinline__ void gemm_body(
    char* smem,
    const __nv_bfloat16* __restrict__ a_h, const __nv_bfloat16* __restrict__ a_l,
    const __nv_bfloat16* __restrict__ b_h, const __nv_bfloat16* __restrict__ b_l,
    const float* __restrict__ bias, float* __restrict__ Y,
    int G, int b0, int g0)
{
    int tid  = threadIdx.x;
    int wid  = tid >> 5;
    int lane = tid & 31;
    uint32_t sb = smem_u32(smem);

    fill_half(sb, tid, 0, a_h, a_l, b_h, b_l);
    CP_COMMIT();
    fill_half(sb, tid, 1, a_h, a_l, b_h, b_l);
    CP_COMMIT();

    int wm = (wid & 3) * 32;
    int wn = (wid >> 2) * 32;

    int a_lane = (wm + (lane & 7) + ((lane >> 3) & 1) * 8) * ROWB + (lane >> 4) * 16;
    int b_lane = (wn + (lane & 7) + ((lane >> 4) & 1) * 8) * ROWB + ((lane >> 3) & 1) * 16;

    uint32_t aH = sb + SM_AH + a_lane;
    uint32_t aL = sb + SM_AL + a_lane;
    uint32_t bH = sb + SM_BH + b_lane;
    uint32_t bL = sb + SM_BL + b_lane;

    float acc[2][4][4];
    #pragma unroll
    for (int i = 0; i < 2; i++)
        #pragma unroll
        for (int j = 0; j < 4; j++)
            #pragma unroll
            for (int r = 0; r < 4; r++) acc[i][j][r] = 0.0f;

    Frags fr[2];

    CP_WAIT(1);
    __syncthreads();
    ld_frags(fr[0], aH, aL, bH, bL);
    #pragma unroll
    for (int kk = 0; kk < 4; kk++) {
        if (kk < 3) {
            int ko = (kk + 1) * 32;
            ld_frags(fr[(kk + 1) & 1], aH + ko, aL + ko, bH + ko, bL + ko);
        }
        mma_all(acc, fr[kk & 1]);
    }

    CP_WAIT(0);
    __syncthreads();
    ld_frags(fr[0], aH + 128, aL + 128, bH + 128, bL + 128);
    #pragma unroll
    for (int kk = 0; kk < 4; kk++) {
        if (kk < 3) {
            int ko = 128 + (kk + 1) * 32;
            ld_frags(fr[(kk + 1) & 1], aH + ko, aL + ko, bH + ko, bL + ko);
        }
        mma_all(acc, fr[kk & 1]);
    }

    int colb = g0 + wn + (lane & 3) * 2;
    #pragma unroll
    for (int i = 0; i < 2; i++) {
        int row = b0 + wm + i * 16 + (lane >> 2);
        #pragma unroll
        for (int j = 0; j < 4; j++) {
            int col = colb + j * 8;
            float bx = bias[col], by = bias[col + 1];
            float2 o0 = make_float2(acc[i][j][0] + bx, acc[i][j][1] + by);
            float2 o1 = make_float2(acc[i][j][2] + bx, acc[i][j][3] + by);
            *reinterpret_cast<float2*>(Y + (long)row * G + col)       = o0;
            *reinterpret_cast<float2*>(Y + (long)(row + 8) * G + col) = o1;
        }
    }
}

__global__ __launch_bounds__(256, 2) void gemm_tc(
    const __nv_bfloat16* __restrict__ Ah, const __nv_bfloat16* __restrict__ Al,
    const __nv_bfloat16* __restrict__ Bh, const __nv_bfloat16* __restrict__ Bl,
    const float* __restrict__ bias, float* __restrict__ Y,
    int G, long xStride, long wStride, long bStride, long yStride)
{
    extern __shared__ char smem[];
    int c = blockIdx.z;
    int b0 = blockIdx.x * 128;
    int g0 = blockIdx.y * 64;
    gemm_body(smem,
              Ah + (long)c * xStride + (long)b0 * 128,
              Al + (long)c * xStride + (long)b0 * 128,
              Bh + (long)c * wStride + (long)g0 * 128,
              Bl + (long)c * wStride + (long)g0 * 128,
              bias + (long)c * bStride,
              Y + (long)c * yStride, G, b0, g0);
}

// ======================= fused gh-GEMM + GRU =======================
// CTA tile 128(b) x 48 permuted cols (16 hidden units), 256 thr, 8 warps
// (4m x 2n, warp 32x24). smem 95744B -> 2 CTAs/SM. After mainloop, acc is
// staged to smem (B slot, fp32 stride 50 = even -> float2 stays aligned),
// epilogue adds gh bias, reads permuted gi from DRAM (or bias broadcast for
// l=0 c>0), runs GRU, writes hn + bf16 splits.
#define F2_AH   0
#define F2_AL   34816
#define F2_BH   69632
#define F2_BL   (69632 + 48 * ROWB)         // 82688
#define F2_TOT  (69632 + 2 * 48 * ROWB)     // 95744
#define F2_STG  69632                        // fp32 stage, stride 50 floats (25600B <= 26112B)
#define STG_W   50

struct Frag2 {
    uint32_t ah[2][4];
    uint32_t al[2][4];
    uint32_t bh[3][2];
    uint32_t bl[3][2];
};

__device__ __forceinline__ void ld_frags2(Frag2& f, uint32_t aH, uint32_t aL,
                                          uint32_t bH4, uint32_t bL4,
                                          uint32_t bH2, uint32_t bL2) {
    #pragma unroll
    for (int i = 0; i < 2; i++)
        LDSM_X4(f.ah[i][0], f.ah[i][1], f.ah[i][2], f.ah[i][3], aH + i * (16 * ROWB));
    #pragma unroll
    for (int i = 0; i < 2; i++)
        LDSM_X4(f.al[i][0], f.al[i][1], f.al[i][2], f.al[i][3], aL + i * (16 * ROWB));
    LDSM_X4(f.bh[0][0], f.bh[0][1], f.bh[1][0], f.bh[1][1], bH4);
    LDSM_X2(f.bh[2][0], f.bh[2][1], bH2);
    LDSM_X4(f.bl[0][0], f.bl[0][1], f.bl[1][0], f.bl[1][1], bL4);
    LDSM_X2(f.bl[2][0], f.bl[2][1], bL2);
}

__device__ __forceinline__ void mma_all2(float acc[2][3][4], Frag2& f) {
    #pragma unroll
    for (int i = 0; i < 2; i++)
        #pragma unroll
        for (int j = 0; j < 3; j++)
            mma16816(acc[i][j], f.ah[i], f.bh[j]);
    #pragma unroll
    for (int i = 0; i < 2; i++)
        #pragma unroll
        for (int j = 0; j < 3; j++)
            mma16816(acc[i][j], f.ah[i], f.bl[j]);
    #pragma unroll
    for (int i = 0; i < 2; i++)
        #pragma unroll
        for (int j = 0; j < 3; j++)
            mma16816(acc[i][j], f.al[i], f.bh[j]);
}

__device__ __forceinline__ void fill_half2(
    uint32_t sb, int tid, int h,
    const __nv_bfloat16* a_h, const __nv_bfloat16* a_l,
    const __nv_bfloat16* b_h, const __nv_bfloat16* b_l)
{
    #pragma unroll 2
    for (int idx = tid; idx < 1024; idx += 256) {        // A: 128 rows x 8 chunks
        int r = idx >> 3, k = (idx & 7) + h * 8;
        cpa16(sb + F2_AH + r * ROWB + k * 16, a_h + (long)r * 128 + k * 8);
        cpa16(sb + F2_AL + r * ROWB + k * 16, a_l + (long)r * 128 + k * 8);
    }
    #pragma unroll 2
    for (int idx = tid; idx < 384; idx += 256) {         // B: 48 rows x 8 chunks
        int r = idx >> 3, k = (idx & 7) + h * 8;
        cpa16(sb + F2_BH + r * ROWB + k * 16, b_h + (long)r * 128 + k * 8);
        cpa16(sb + F2_BL + r * ROWB + k * 16, b_l + (long)r * 128 + k * 8);
    }
}

__global__ __launch_bounds__(256, 2) void gh_gru(
    const __nv_bfloat16* __restrict__ hhH, const __nv_bfloat16* __restrict__ hhL,
    const __nv_bfloat16* __restrict__ whH, const __nv_bfloat16* __restrict__ whL,
    const float* __restrict__ bhP,
    const float* __restrict__ giBuf,
    const float* __restrict__ biP,
    const float* __restrict__ hprev,
    float* __restrict__ hnOut,
    __nv_bfloat16* __restrict__ nhOut, __nv_bfloat16* __restrict__ nlOut,
    int l0flag)
{
    extern __shared__ char smem[];
    uint32_t sb = smem_u32(smem);

    int b0 = blockIdx.x * 128;
    int g0 = blockIdx.y * 48;          // permuted col base
    int c  = blockIdx.z;
    int tid = threadIdx.x, wid = tid >> 5, lane = tid & 31;

    const __nv_bfloat16* a_h = hhH + ((long)c * Bsz + b0) * 128;
    const __nv_bfloat16* a_l = hhL + ((long)c * Bsz + b0) * 128;
    const __nv_bfloat16* b_h = whH + (long)c * ((long)G3H * Hd) + (long)g0 * 128;
    const __nv_bfloat16* b_l = whL + (long)c * ((long)G3H * Hd) + (long)g0 * 128;

    fill_half2(sb, tid, 0, a_h, a_l, b_h, b_l);
    CP_COMMIT();
    fill_half2(sb, tid, 1, a_h, a_l, b_h, b_l);
    CP_COMMIT();

    int wm = (wid & 3) * 32;
    int wn = (wid >> 2) * 24;

    int a_lane  = (wm + (lane & 7) + ((lane >> 3) & 1) * 8) * ROWB + (lane >> 4) * 16;
    int b_lane4 = (wn + (lane & 7) + ((lane >> 4) & 1) * 8) * ROWB + ((lane >> 3) & 1) * 16;
    int l15 = lane & 15;
    int b_lane2 = (wn + 16 + (l15 & 7)) * ROWB + ((l15 >> 3) & 1) * 16;

    uint32_t aH  = sb + F2_AH + a_lane;
    uint32_t aL  = sb + F2_AL + a_lane;
    uint32_t bH4 = sb + F2_BH + b_lane4;
    uint32_t bL4 = sb + F2_BL + b_lane4;
    uint32_t bH2 = sb + F2_BH + b_lane2;
    uint32_t bL2 = sb + F2_BL + b_lane2;

    float acc[2][3][4];
    #pragma unroll
    for (int i = 0; i < 2; i++)
        #pragma unroll
        for (int j = 0; j < 3; j++)
            #pragma unroll
            for (int r = 0; r < 4; r++) acc[i][j][r] = 0.0f;

    Frag2 fr[2];

    CP_WAIT(1);
    __syncthreads();
    ld_frags2(fr[0], aH, aL, bH4, bL4, bH2, bL2);
    #pragma unroll
    for (int kk = 0; kk < 4; kk++) {
        if (kk < 3) {
            int ko = (kk + 1) * 32;
            ld_frags2(fr[(kk + 1) & 1], aH + ko, aL + ko,
                      bH4 + ko, bL4 + ko, bH2 + ko, bL2 + ko);
        }
        mma_all2(acc, fr[kk & 1]);
    }

    CP_WAIT(0);
    __syncthreads();
    ld_frags2(fr[0], aH + 128, aL + 128, bH4 + 128, bL4 + 128, bH2 + 128, bL2 + 128);
    #pragma unroll
    for (int kk = 0; kk < 4; kk++) {
        if (kk < 3) {
            int ko = 128 + (kk + 1) * 32;
            ld_frags2(fr[(kk + 1) & 1], aH + ko, aL + ko,
                      bH4 + ko, bL4 + ko, bH2 + ko, bL2 + ko);
        }
        mma_all2(acc, fr[kk & 1]);
    }

    // ---- stage acc (raw gh, no bias) to smem: 128 x 48 fp32, stride 50 ----
    __syncthreads();    // everyone done reading B tiles
    float* stg = reinterpret_cast<float*>(smem + F2_STG);
    #pragma unroll
    for (int i = 0; i < 2; i++) {
        int row = wm + i * 16 + (lane >> 2);
        #pragma unroll
        for (int j = 0; j < 3; j++) {
            int col = wn + (lane & 3) * 2 + j * 8;
            *reinterpret_cast<float2*>(&stg[row * STG_W + col]) =
                make_float2(acc[i][j][0], acc[i][j][1]);
            *reinterpret_cast<float2*>(&stg[(row + 8) * STG_W + col]) =
                make_float2(acc[i][j][2], acc[i][j][3]);
        }
    }
    __syncthreads();

    // ---- GRU epilogue: 128 rows x 16 units ----
    bool biasGi = (l0flag != 0) && (c > 0);
    #pragma unroll
    for (int it = 0; it < 8; it++) {
        int item = tid + it * 256;       // 2048 items
        int row = item >> 4;
        int u   = item & 15;
        int col = 3 * u;

        long bb = (long)c * G3H + g0 + col;
        float hrv = stg[row * STG_W + col]     + bhP[bb];
        float hzv = stg[row * STG_W + col + 1] + bhP[bb + 1];
        float hnv = stg[row * STG_W + col + 2] + bhP[bb + 2];

        float irv, izv, inv;
        if (biasGi) {
            irv = biP[bb];
            izv = biP[bb + 1];
            inv = biP[bb + 2];
        } else {
            const float* gp = giBuf + ((long)c * Bsz + b0 + row) * G3H + g0 + col;
            irv = gp[0];
            izv = gp[1];
            inv = gp[2];
        }

        float rr = sigf(irv + hrv);
        float zz = sigf(izv + hzv);
        float nn = tanhf(inv + rr * hnv);

        int hgl = blockIdx.y * 16 + u;
        long go = ((long)c * Bsz + b0 + row) * 128 + hgl;
        float hp = hprev[go];
        float out = (1.0f - zz) * nn + zz * hp;
        hnOut[go] = out;
        __nv_bfloat16 oh = __float2bfloat16(out);
        nhOut[go] = oh;
        nlOut[go] = __float2bfloat16(out - __bfloat162float(oh));
    }
}

// ---------------- embedding gather -> bf16 hi/lo split -----------------------
__global__ void gather_x0(const int* __restrict__ tok, const float* __restrict__ emb)
{
    long t = (long)blockIdx.x * 256 + threadIdx.x;   // B*32 threads
    int b  = (int)(t >> 5);
    int e4 = (int)(t & 31) << 2;
    float4 v = *(const float4*)(emb + (long)tok[b] * 128 + e4);
    store_split4(g_x0h, g_x0l, (long)b * 128 + e4, v);
}

// ---------------- tiny attention over C=4 positions -> bf16 split ------------
__global__ void attn_kernel()
{
    int gw   = blockIdx.x * 4 + (threadIdx.x >> 5);
    int lane = threadIdx.x & 31;
    int b  = gw >> 2;
    int nh = gw & 3;

    float q[4], k[4], v[4];
    #pragma unroll
    for (int c = 0; c < 4; c++) {
        const float* p = g_qkv + ((long)c * Bsz + b) * G3H + nh * 32 + lane;
        q[c] = p[0];
        k[c] = p[128];
        v[c] = p[256];
    }

    float s[4][4];
    #pragma unroll
    for (int qc = 0; qc < 4; qc++) {
        #pragma unroll
        for (int kc = 0; kc < 4; kc++) {
            float p = q[qc] * k[kc];
            #pragma unroll
            for (int off = 16; off > 0; off >>= 1)
                p += __shfl_xor_sync(0xFFFFFFFFu, p, off);
            s[qc][kc] = p * 0.17677669529663687f;   // 1/sqrt(32)
        }
    }

    #pragma unroll
    for (int qc = 0; qc < 4; qc++) {
        float m = fmaxf(fmaxf(s[qc][0], s[qc][1]), fmaxf(s[qc][2], s[qc][3]));
        float e0 = expf(s[qc][0] - m), e1 = expf(s[qc][1] - m);
        float e2 = expf(s[qc][2] - m), e3 = expf(s[qc][3] - m);
        float inv = 1.0f / (e0 + e1 + e2 + e3);
        float o = (e0 * v[0] + e1 * v[1] + e2 * v[2] + e3 * v[3]) * inv;
        long off = ((long)qc * Bsz + b) * 128 + nh * 32 + lane;
        __nv_bfloat16 h = __float2bfloat16(o);
        g_aah[off] = h;
        g_aal[off] = __float2bfloat16(o - __bfloat162float(h));
    }
}

// ---------------- fused LayerNorm + gate + blend -----------------------------
__global__ void lngate_kernel(const float* __restrict__ gg, const float* __restrict__ bb,
                              const float* __restrict__ gw, const float* __restrict__ gbp,
                              float* __restrict__ hout)
{
    int row  = blockIdx.x * 4 + (threadIdx.x >> 5);
    int lane = threadIdx.x & 31;
    const float* mp = g_msg + (long)row * 128;
    const float* hp = g_hn  + (long)row * 128;

    float4 x = *(const float4*)(mp + lane * 4);
    float s = x.x + x.y + x.z + x.w;
    #pragma unroll
    for (int off = 16; off > 0; off >>= 1) s += __shfl_xor_sync(0xFFFFFFFFu, s, off);
    float mean = s * (1.0f / 128.0f);

    float dx = x.x - mean, dy = x.y - mean, dz = x.z - mean, dw = x.w - mean;
    float sq = dx * dx + dy * dy + dz * dz + dw * dw;
    #pragma unroll
    for (int off = 16; off > 0; off >>= 1) sq += __shfl_xor_sync(0xFFFFFFFFu, sq, off);
    float rstd = rsqrtf(sq * (1.0f / 128.0f) + 1e-5f);

    float4 gv = *(const float4*)(gg + lane * 4);
    float4 bv = *(const float4*)(bb + lane * 4);
    float4 m;
    m.x = dx * rstd * gv.x + bv.x;
    m.y = dy * rstd * gv.y + bv.y;
    m.z = dz * rstd * gv.z + bv.z;
    m.w = dw * rstd * gv.w + bv.w;

    float4 hv = *(const float4*)(hp + lane * 4);
    float4 w1 = *(const float4*)(gw + lane * 4);
    float4 w2 = *(const float4*)(gw + 128 + lane * 4);

    float p = hv.x * w1.x + hv.y * w1.y + hv.z * w1.z + hv.w * w1.w
            + m.x * w2.x + m.y * w2.y + m.z * w2.z + m.w * w2.w;
    #pragma unroll
    for (int off = 16; off > 0; off >>= 1) p += __shfl_xor_sync(0xFFFFFFFFu, p, off);
    float gt = sigf(p + gbp[0]);

    float4 o;
    o.x = (1.0f - gt) * hv.x + gt * m.x;
    o.y = (1.0f - gt) * hv.y + gt * m.y;
    o.z = (1.0f - gt) * hv.z + gt * m.z;
    o.w = (1.0f - gt) * hv.w + gt * m.w;
    long off = (long)row * 128 + lane * 4;
    *(float4*)(hout + off) = o;
    store_split4(g_ph, g_pl, off, o);
}

// ---------------- host orchestration ----------------------------------------
extern "C" void kernel_launch(void* const* d_in, const int* in_sizes, int n_in,
                              void* d_out, int out_size)
{
    const int*   tokens     = (const int*)  d_in[0];
    const float* h_in       = (const float*)d_in[1];
    const float* emb        = (const float*)d_in[2];
    const float* wih0_c0    = (const float*)d_in[3];
    const float* bih0       = (const float*)d_in[5];
    const float* whh0       = (const float*)d_in[6];
    const float* bhh0       = (const float*)d_in[7];
    const float* wih        = (const float*)d_in[8];
    const float* whh        = (const float*)d_in[9];
    const float* bih        = (const float*)d_in[10];
    const float* bhh        = (const float*)d_in[11];
    const float* attn_in_w  = (const float*)d_in[12];
    const float* attn_in_b  = (const float*)d_in[13];
    const float* attn_out_w = (const float*)d_in[14];
    const float* attn_out_b = (const float*)d_in[15];
    const float* ln_g       = (const float*)d_in[16];
    const float* ln_b       = (const float*)d_in[17];
    const float* gate_w     = (const float*)d_in[18];
    const float* gate_b     = (const float*)d_in[19];
    const float* head_w     = (const float*)d_in[20];
    const float* head_b     = (const float*)d_in[21];

    float* yOut = (float*)d_out;                       // (B, O)
    float* hOut = yOut + (size_t)Bsz * Oo;             // (L, C, B, H)

    float *pgi, *pqkv, *phn, *pmsg;
    cudaGetSymbolAddress((void**)&pgi,  g_gi);
    cudaGetSymbolAddress((void**)&pqkv, g_qkv);
    cudaGetSymbolAddress((void**)&phn,  g_hn);
    cudaGetSymbolAddress((void**)&pmsg, g_msg);

    __nv_bfloat16 *x0h, *x0l, *hh, *hl, *nh, *nl, *aah, *aal, *ph, *pl;
    __nv_bfloat16 *wih0h, *wih0l, *whh0h, *whh0l, *wihh, *wihl, *whhh, *whhl;
    __nv_bfloat16 *aiwh, *aiwl, *aowh, *aowl, *hwh, *hwl;
    float *bih0P, *bhh0P, *bihP, *bhhP;
    cudaGetSymbolAddress((void**)&x0h, g_x0h);   cudaGetSymbolAddress((void**)&x0l, g_x0l);
    cudaGetSymbolAddress((void**)&hh,  g_hh);    cudaGetSymbolAddress((void**)&hl,  g_hl);
    cudaGetSymbolAddress((void**)&nh,  g_nh);    cudaGetSymbolAddress((void**)&nl,  g_nl);
    cudaGetSymbolAddress((void**)&aah, g_aah);   cudaGetSymbolAddress((void**)&aal, g_aal);
    cudaGetSymbolAddress((void**)&ph,  g_ph);    cudaGetSymbolAddress((void**)&pl,  g_pl);
    cudaGetSymbolAddress((void**)&wih0h, g_wih0h); cudaGetSymbolAddress((void**)&wih0l, g_wih0l);
    cudaGetSymbolAddress((void**)&whh0h, g_whh0h); cudaGetSymbolAddress((void**)&whh0l, g_whh0l);
    cudaGetSymbolAddress((void**)&wihh, g_wihh); cudaGetSymbolAddress((void**)&wihl, g_wihl);
    cudaGetSymbolAddress((void**)&whhh, g_whhh); cudaGetSymbolAddress((void**)&whhl, g_whhl);
    cudaGetSymbolAddress((void**)&aiwh, g_aiwh); cudaGetSymbolAddress((void**)&aiwl, g_aiwl);
    cudaGetSymbolAddress((void**)&aowh, g_aowh); cudaGetSymbolAddress((void**)&aowl, g_aowl);
    cudaGetSymbolAddress((void**)&hwh,  g_hwh);  cudaGetSymbolAddress((void**)&hwl,  g_hwl);
    cudaGetSymbolAddress((void**)&bih0P, g_bih0P); cudaGetSymbolAddress((void**)&bhh0P, g_bhh0P);
    cudaGetSymbolAddress((void**)&bihP,  g_bihP);  cudaGetSymbolAddress((void**)&bhhP,  g_bhhP);

    cudaFuncSetAttribute(gemm_tc, cudaFuncAttributeMaxDynamicSharedMemorySize, SM_TOT);
    cudaFuncSetAttribute(gh_gru,  cudaFuncAttributeMaxDynamicSharedMemorySize, F2_TOT);

    const long CBH = (long)Cc * Bsz * Hd;
    (void)in_sizes; (void)n_in; (void)out_size;

    // ---- prolog ----
    // gate weights: permute + split; gate biases: permute
    permute_split_w<<<(int)(((long)G3H * Hd / 4) / 256), 256>>>(wih0_c0, wih0h, wih0l);
    permute_split_w<<<(int)(((long)Cc * G3H * Hd / 4) / 256), 256>>>(whh0, whh0h, whh0l);
    permute_split_w<<<(int)(((long)(Ll-1) * Cc * G3H * Hd / 4) / 256), 256>>>(wih, wihh, wihl);
    permute_split_w<<<(int)(((long)(Ll-1) * Cc * G3H * Hd / 4) / 256), 256>>>(whh, whhh, whhl);
    permute_bias<<<(Cc * G3H + 255) / 256, 256>>>(bih0, bih0P, Cc * G3H);
    permute_bias<<<(Cc * G3H + 255) / 256, 256>>>(bhh0, bhh0P, Cc * G3H);
    permute_bias<<<((Ll-1) * Cc * G3H + 255) / 256, 256>>>(bih, bihP, (Ll-1) * Cc * G3H);
    permute_bias<<<((Ll-1) * Cc * G3H + 255) / 256, 256>>>(bhh, bhhP, (Ll-1) * Cc * G3H);
    // plain splits for attention / head weights and h
    split_pair<<<(int)(((long)Ll * G3H * Hd / 4) / 256), 256>>>(attn_in_w, aiwh, aiwl);
    split_pair<<<(int)(((long)Ll * Hd * Hd / 4) / 256), 256>>>(attn_out_w, aowh, aowl);
    split_pair<<<(int)(((long)Oo * Hd / 4) / 256), 256>>>(head_w, hwh, hwl);
    split_pair<<<(int)(((long)Ll * CBH / 4) / 256), 256>>>(h_in, hh, hl);
    gather_x0<<<(Bsz * 32) / 256, 256>>>(tokens, emb);

    dim3 gB(Bsz / 128, G3H / 64, Cc);
    dim3 gO(Bsz / 128, Hd  / 64, Cc);
    dim3 gG(Bsz / 128, G3H / 48, Cc);   // fused gh+GRU grid (y = 8)

    for (int l = 0; l < Ll; l++) {
        // ---- gi (permuted) ----
        if (l == 0) {
            dim3 g1(Bsz / 128, G3H / 64, 1);
            gemm_tc<<<g1, 256, SM_TOT>>>(x0h, x0l, wih0h, wih0l, bih0P, pgi,
                                         G3H, 0, 0, 0, 0);
        } else {
            gemm_tc<<<gB, 256, SM_TOT>>>(ph, pl,
                                         wihh + (size_t)(l - 1) * Cc * G3H * Hd,
                                         wihl + (size_t)(l - 1) * Cc * G3H * Hd,
                                         bihP + (size_t)(l - 1) * Cc * G3H,
                                         pgi, G3H,
                                         (long)Bsz * Hd, (long)G3H * Hd, G3H, (long)Bsz * G3H);
        }

        // ---- fused gh GEMM + GRU ----
        const __nv_bfloat16* whh_h = (l == 0) ? whh0h : whhh + (size_t)(l - 1) * Cc * G3H * Hd;
        const __nv_bfloat16* whh_l = (l == 0) ? whh0l : whhl + (size_t)(l - 1) * Cc * G3H * Hd;
        const float* bhP_l = (l == 0) ? bhh0P : bhhP + (size_t)(l - 1) * Cc * G3H;
        gh_gru<<<gG, 256, F2_TOT>>>(hh + (size_t)l * CBH, hl + (size_t)l * CBH,
                                    whh_h, whh_l, bhP_l,
                                    pgi, bih0P,
                                    h_in + (size_t)l * CBH,
                                    phn, nh, nl, l == 0 ? 1 : 0);

        // ---- QKV ----
        gemm_tc<<<gB, 256, SM_TOT>>>(nh, nl,
                                     aiwh + (size_t)l * G3H * Hd,
                                     aiwl + (size_t)l * G3H * Hd,
                                     attn_in_b + (size_t)l * G3H,
                                     pqkv, G3H,
                                     (long)Bsz * Hd, 0, 0, (long)Bsz * G3H);

        // ---- attention ----
        attn_kernel<<<(Bsz * NHh) / 4, 128>>>();

        // ---- out projection ----
        gemm_tc<<<gO, 256, SM_TOT>>>(aah, aal,
                                     aowh + (size_t)l * Hd * Hd,
                                     aowl + (size_t)l * Hd * Hd,
                                     attn_out_b + (size_t)l * Hd,
                                     pmsg, Hd,
                                     (long)Bsz * Hd, 0, 0, (long)Bsz * Hd);

        // ---- fused LN + gate + blend -> hOut + g_ph/g_pl split ----
        lngate_kernel<<<(Cc * Bsz) / 4, 128>>>(ln_g + (size_t)l * Hd, ln_b + (size_t)l * Hd,
                                               gate_w + (size_t)l * 2 * Hd, gate_b + l,
                                               hOut + (size_t)l * CBH);
    }

    // ---- head: y = h_n[L-1, 0] @ head_w.T + head_b ----
    dim3 gH(Bsz / 128, Oo / 64, 1);
    gemm_tc<<<gH, 256, SM_TOT>>>(ph, pl, hwh, hwl, head_b, yOut, Oo, 0, 0, 0, 0);
}

// round 13
// speedup vs baseline: 1.1398x; 1.1398x over previous
#include <cuda_runtime.h>
#include <cuda_bf16.h>
#include <math.h>
#include <stdint.h>

#define Bsz 16384
#define Hd  128
#define Cc  4
#define Ll  6
#define NHh 4
#define HDd 32
#define Oo  1024
#define G3H 384

// ---------------- fp32 scratch ----------------------------------------------
__device__ __align__(256) float g_gi [(size_t)Cc * Bsz * G3H];
__device__ __align__(256) float g_gh [(size_t)Cc * Bsz * G3H];
__device__ __align__(256) float g_qkv[(size_t)Cc * Bsz * G3H];
__device__ __align__(256) float g_msg[(size_t)Cc * Bsz * Hd];

// ---------------- bf16 hi/lo split buffers ----------------------------------
__device__ __align__(256) __nv_bfloat16 g_x0h[(size_t)Bsz * Hd];
__device__ __align__(256) __nv_bfloat16 g_x0l[(size_t)Bsz * Hd];
__device__ __align__(256) __nv_bfloat16 g_hh [(size_t)Ll * Cc * Bsz * Hd];  // h_in split
__device__ __align__(256) __nv_bfloat16 g_hl [(size_t)Ll * Cc * Bsz * Hd];
__device__ __align__(256) __nv_bfloat16 g_nh [(size_t)Cc * Bsz * Hd];       // hn split
__device__ __align__(256) __nv_bfloat16 g_nl [(size_t)Cc * Bsz * Hd];
__device__ __align__(256) __nv_bfloat16 g_aah[(size_t)Cc * Bsz * Hd];       // att split
__device__ __align__(256) __nv_bfloat16 g_aal[(size_t)Cc * Bsz * Hd];
__device__ __align__(256) __nv_bfloat16 g_ph [(size_t)Cc * Bsz * Hd];       // hOut split
__device__ __align__(256) __nv_bfloat16 g_pl [(size_t)Cc * Bsz * Hd];
// weights
__device__ __align__(256) __nv_bfloat16 g_wih0h[(size_t)G3H * Hd];
__device__ __align__(256) __nv_bfloat16 g_wih0l[(size_t)G3H * Hd];
__device__ __align__(256) __nv_bfloat16 g_whh0h[(size_t)Cc * G3H * Hd];
__device__ __align__(256) __nv_bfloat16 g_whh0l[(size_t)Cc * G3H * Hd];
__device__ __align__(256) __nv_bfloat16 g_wihh[(size_t)(Ll-1) * Cc * G3H * Hd];
__device__ __align__(256) __nv_bfloat16 g_wihl[(size_t)(Ll-1) * Cc * G3H * Hd];
__device__ __align__(256) __nv_bfloat16 g_whhh[(size_t)(Ll-1) * Cc * G3H * Hd];
__device__ __align__(256) __nv_bfloat16 g_whhl[(size_t)(Ll-1) * Cc * G3H * Hd];
__device__ __align__(256) __nv_bfloat16 g_aiwh[(size_t)Ll * G3H * Hd];
__device__ __align__(256) __nv_bfloat16 g_aiwl[(size_t)Ll * G3H * Hd];
__device__ __align__(256) __nv_bfloat16 g_aowh[(size_t)Ll * Hd * Hd];
__device__ __align__(256) __nv_bfloat16 g_aowl[(size_t)Ll * Hd * Hd];
__device__ __align__(256) __nv_bfloat16 g_hwh [(size_t)Oo * Hd];
__device__ __align__(256) __nv_bfloat16 g_hwl [(size_t)Oo * Hd];

__device__ __forceinline__ float sigf(float x) { return 1.0f / (1.0f + expf(-x)); }

__device__ __forceinline__ uint32_t pack_bf16(__nv_bfloat16 a, __nv_bfloat16 b) {
    __nv_bfloat162 t = __nv_bfloat162(a, b);
    return *reinterpret_cast<uint32_t*>(&t);
}

__device__ __forceinline__ void store_split4(__nv_bfloat16* ph, __nv_bfloat16* pl,
                                             long off, float4 v) {
    __nv_bfloat16 h0 = __float2bfloat16(v.x);
    __nv_bfloat16 h1 = __float2bfloat16(v.y);
    __nv_bfloat16 h2 = __float2bfloat16(v.z);
    __nv_bfloat16 h3 = __float2bfloat16(v.w);
    *reinterpret_cast<uint2*>(ph + off) =
        make_uint2(pack_bf16(h0, h1), pack_bf16(h2, h3));
    __nv_bfloat16 l0 = __float2bfloat16(v.x - __bfloat162float(h0));
    __nv_bfloat16 l1 = __float2bfloat16(v.y - __bfloat162float(h1));
    __nv_bfloat16 l2 = __float2bfloat16(v.z - __bfloat162float(h2));
    __nv_bfloat16 l3 = __float2bfloat16(v.w - __bfloat162float(h3));
    *reinterpret_cast<uint2*>(pl + off) =
        make_uint2(pack_bf16(l0, l1), pack_bf16(l2, l3));
}

// load 4 consecutive split values and reconstruct fp32 (hi + lo)
__device__ __forceinline__ float4 load_split4(const __nv_bfloat16* ph,
                                              const __nv_bfloat16* pl, long off) {
    uint2 uh = *reinterpret_cast<const uint2*>(ph + off);
    uint2 ul = *reinterpret_cast<const uint2*>(pl + off);
    __nv_bfloat162 h01 = *reinterpret_cast<__nv_bfloat162*>(&uh.x);
    __nv_bfloat162 h23 = *reinterpret_cast<__nv_bfloat162*>(&uh.y);
    __nv_bfloat162 l01 = *reinterpret_cast<__nv_bfloat162*>(&ul.x);
    __nv_bfloat162 l23 = *reinterpret_cast<__nv_bfloat162*>(&ul.y);
    float4 v;
    v.x = __bfloat162float(h01.x) + __bfloat162float(l01.x);
    v.y = __bfloat162float(h01.y) + __bfloat162float(l01.y);
    v.z = __bfloat162float(h23.x) + __bfloat162float(l23.x);
    v.w = __bfloat162float(h23.y) + __bfloat162float(l23.y);
    return v;
}

// ---------------- generic fp32 -> bf16 hi/lo split pass ---------------------
__global__ void split_pair(const float* __restrict__ in, __nv_bfloat16* __restrict__ oh,
                           __nv_bfloat16* __restrict__ ol)
{
    long i = (long)blockIdx.x * 256 + threadIdx.x;   // float4 index
    float4 v = reinterpret_cast<const float4*>(in)[i];
    store_split4(oh, ol, i * 4, v);
}

// ======================= HMMA (mma.sync) GEMM =======================
// CTA tile 128(b) x 64(g), 256 threads, 8 warps (4m x 2n), warp tile 32x32,
// 2 CTAs/SM. Term-major MMA ordering; 2-stage pipelined k-split fill.

#define KPAD    136
#define ROWB    (KPAD * 2)            // 272 bytes per row
#define TILE_A  ((size_t)128 * ROWB)
#define TILE_Bt ((size_t)64  * ROWB)
#define SM_AH   0
#define SM_AL   (SM_AH + TILE_A)
#define SM_BH   (SM_AL + TILE_A)
#define SM_BL   (SM_BH + TILE_Bt)
#define SM_TOT  (SM_BL + TILE_Bt)     // 104448 bytes

__device__ __forceinline__ uint32_t smem_u32(const void* p) {
    uint32_t a;
    asm("{ .reg .u64 t; cvta.to.shared.u64 t, %1; cvt.u32.u64 %0, t; }" : "=r"(a) : "l"(p));
    return a;
}
__device__ __forceinline__ void cpa16(uint32_t sdst, const void* gsrc) {
    asm volatile("cp.async.cg.shared.global [%0], [%1], 16;" :: "r"(sdst), "l"(gsrc));
}
#define CP_COMMIT() asm volatile("cp.async.commit_group;" ::: "memory")
#define CP_WAIT(n)  asm volatile("cp.async.wait_group %0;" :: "n"(n) : "memory")

__device__ __forceinline__ void mma16816(float* c, const uint32_t* a, const uint32_t* b) {
    asm volatile(
        "mma.sync.aligned.m16n8k16.row.col.f32.bf16.bf16.f32 "
        "{%0,%1,%2,%3}, {%4,%5,%6,%7}, {%8,%9}, {%0,%1,%2,%3};\n"
        : "+f"(c[0]), "+f"(c[1]), "+f"(c[2]), "+f"(c[3])
        : "r"(a[0]), "r"(a[1]), "r"(a[2]), "r"(a[3]), "r"(b[0]), "r"(b[1]));
}

#define LDSM_X4(r0, r1, r2, r3, addr) \
    asm volatile("ldmatrix.sync.aligned.m8n8.x4.shared.b16 {%0,%1,%2,%3}, [%4];" \
                 : "=r"(r0), "=r"(r1), "=r"(r2), "=r"(r3) : "r"(addr))

struct Frags {
    uint32_t ah[2][4];
    uint32_t al[2][4];
    uint32_t bh[4][2];
    uint32_t bl[4][2];
};

__device__ __forceinline__ void ld_frags(Frags& f, uint32_t aH, uint32_t aL,
                                         uint32_t bH, uint32_t bL) {
    #pragma unroll
    for (int i = 0; i < 2; i++)
        LDSM_X4(f.ah[i][0], f.ah[i][1], f.ah[i][2], f.ah[i][3], aH + i * (16 * ROWB));
    #pragma unroll
    for (int i = 0; i < 2; i++)
        LDSM_X4(f.al[i][0], f.al[i][1], f.al[i][2], f.al[i][3], aL + i * (16 * ROWB));
    LDSM_X4(f.bh[0][0], f.bh[0][1], f.bh[1][0], f.bh[1][1], bH);
    LDSM_X4(f.bh[2][0], f.bh[2][1], f.bh[3][0], f.bh[3][1], bH + 16 * ROWB);
    LDSM_X4(f.bl[0][0], f.bl[0][1], f.bl[1][0], f.bl[1][1], bL);
    LDSM_X4(f.bl[2][0], f.bl[2][1], f.bl[3][0], f.bl[3][1], bL + 16 * ROWB);
}

__device__ __forceinline__ void mma_all(float acc[2][4][4], Frags& f) {
    // term-major: 8 independent MMAs between accumulator reuses
    #pragma unroll
    for (int i = 0; i < 2; i++)
        #pragma unroll
        for (int j = 0; j < 4; j++)
            mma16816(acc[i][j], f.ah[i], f.bh[j]);
    #pragma unroll
    for (int i = 0; i < 2; i++)
        #pragma unroll
        for (int j = 0; j < 4; j++)
            mma16816(acc[i][j], f.ah[i], f.bl[j]);
    #pragma unroll
    for (int i = 0; i < 2; i++)
        #pragma unroll
        for (int j = 0; j < 4; j++)
            mma16816(acc[i][j], f.al[i], f.bh[j]);
}

// fill one k-half (chunks [h*8, h*8+8) of 16B per row) for A and B tiles
__device__ __forceinline__ void fill_half(
    uint32_t sb, int tid, int h,
    const __nv_bfloat16* a_h, const __nv_bfloat16* a_l,
    const __nv_bfloat16* b_h, const __nv_bfloat16* b_l)
{
    #pragma unroll 2
    for (int idx = tid; idx < 1024; idx += 256) {        // A: 128 rows x 8 chunks
        int r = idx >> 3, k = (idx & 7) + h * 8;
        cpa16(sb + SM_AH + r * ROWB + k * 16, a_h + (long)r * 128 + k * 8);
        cpa16(sb + SM_AL + r * ROWB + k * 16, a_l + (long)r * 128 + k * 8);
    }
    #pragma unroll 2
    for (int idx = tid; idx < 512; idx += 256) {         // B: 64 rows x 8 chunks
        int r = idx >> 3, k = (idx & 7) + h * 8;
        cpa16(sb + SM_BH + r * ROWB + k * 16, b_h + (long)r * 128 + k * 8);
        cpa16(sb + SM_BL + r * ROWB + k * 16, b_l + (long)r * 128 + k * 8);
    }
}

// shared GEMM body: 2-stage pipelined fill, term-major mainloop, epilogue
__device__ __forceinline__ void gemm_body(
    char* smem,
    const __nv_bfloat16* __restrict__ a_h, const __nv_bfloat16* __restrict__ a_l,
    const __nv_bfloat16* __restrict__ b_h, const __nv_bfloat16* __restrict__ b_l,
    const float* __restrict__ bias, float* __restrict__ Y,
    int G, int b0, int g0)
{
    int tid  = threadIdx.x;
    int wid  = tid >> 5;
    int lane = tid & 31;
    uint32_t sb = smem_u32(smem);

    fill_half(sb, tid, 0, a_h, a_l, b_h, b_l);
    CP_COMMIT();
    fill_half(sb, tid, 1, a_h, a_l, b_h, b_l);
    CP_COMMIT();

    int wm = (wid & 3) * 32;
    int wn = (wid >> 2) * 32;

    int a_lane = (wm + (lane & 7) + ((lane >> 3) & 1) * 8) * ROWB + (lane >> 4) * 16;
    int b_lane = (wn + (lane & 7) + ((lane >> 4) & 1) * 8) * ROWB + ((lane >> 3) & 1) * 16;

    uint32_t aH = sb + SM_AH + a_lane;
    uint32_t aL = sb + SM_AL + a_lane;
    uint32_t bH = sb + SM_BH + b_lane;
    uint32_t bL = sb + SM_BL + b_lane;

    float acc[2][4][4];
    #pragma unroll
    for (int i = 0; i < 2; i++)
        #pragma unroll
        for (int j = 0; j < 4; j++)
            #pragma unroll
            for (int r = 0; r < 4; r++) acc[i][j][r] = 0.0f;

    Frags fr[2];

    // ---- first k-half (steps 0..3) ----
    CP_WAIT(1);
    __syncthreads();
    ld_frags(fr[0], aH, aL, bH, bL);
    #pragma unroll
    for (int kk = 0; kk < 4; kk++) {
        if (kk < 3) {
            int ko = (kk + 1) * 32;
            ld_frags(fr[(kk + 1) & 1], aH + ko, aL + ko, bH + ko, bL + ko);
        }
        mma_all(acc, fr[kk & 1]);
    }

    // ---- second k-half (steps 4..7) ----
    CP_WAIT(0);
    __syncthreads();
    ld_frags(fr[0], aH + 128, aL + 128, bH + 128, bL + 128);
    #pragma unroll
    for (int kk = 0; kk < 4; kk++) {
        if (kk < 3) {
            int ko = 128 + (kk + 1) * 32;
            ld_frags(fr[(kk + 1) & 1], aH + ko, aL + ko, bH + ko, bL + ko);
        }
        mma_all(acc, fr[kk & 1]);
    }

    int colb = g0 + wn + (lane & 3) * 2;
    #pragma unroll
    for (int i = 0; i < 2; i++) {
        int row = b0 + wm + i * 16 + (lane >> 2);
        #pragma unroll
        for (int j = 0; j < 4; j++) {
            int col = colb + j * 8;
            float bx = bias[col], by = bias[col + 1];
            float2 o0 = make_float2(acc[i][j][0] + bx, acc[i][j][1] + by);
            float2 o1 = make_float2(acc[i][j][2] + bx, acc[i][j][3] + by);
            *reinterpret_cast<float2*>(Y + (long)row * G + col)       = o0;
            *reinterpret_cast<float2*>(Y + (long)(row + 8) * G + col) = o1;
        }
    }
}

__global__ __launch_bounds__(256, 2) void gemm_tc(
    const __nv_bfloat16* __restrict__ Ah, const __nv_bfloat16* __restrict__ Al,
    const __nv_bfloat16* __restrict__ Bh, const __nv_bfloat16* __restrict__ Bl,
    const float* __restrict__ bias, float* __restrict__ Y,
    int G, long xStride, long wStride, long bStride, long yStride)
{
    extern __shared__ char smem[];
    int c = blockIdx.z;
    int b0 = blockIdx.x * 128;
    int g0 = blockIdx.y * 64;
    gemm_body(smem,
              Ah + (long)c * xStride + (long)b0 * 128,
              Al + (long)c * xStride + (long)b0 * 128,
              Bh + (long)c * wStride + (long)g0 * 128,
              Bl + (long)c * wStride + (long)g0 * 128,
              bias + (long)c * bStride,
              Y + (long)c * yStride, G, b0, g0);
}

// dual-set GEMM: z in [0, 2*Cc); z<Cc -> set1 (gi), else set2 (gh).
__global__ __launch_bounds__(256, 2) void gemm_tc_dual(
    const __nv_bfloat16* __restrict__ A1h, const __nv_bfloat16* __restrict__ A1l,
    const __nv_bfloat16* __restrict__ W1h, const __nv_bfloat16* __restrict__ W1l,
    const float* __restrict__ b1, float* __restrict__ Y1,
    const __nv_bfloat16* __restrict__ A2h, const __nv_bfloat16* __restrict__ A2l,
    const __nv_bfloat16* __restrict__ W2h, const __nv_bfloat16* __restrict__ W2l,
    const float* __restrict__ b2, float* __restrict__ Y2)
{
    extern __shared__ char smem[];
    int z  = blockIdx.z;
    int b0 = blockIdx.x * 128;
    int g0 = blockIdx.y * 64;
    const __nv_bfloat16 *ah, *al, *wh, *wl;
    const float* bias;
    float* Y;
    if (z < Cc) {
        int c = z;
        ah = A1h + (long)c * Bsz * Hd;      al = A1l + (long)c * Bsz * Hd;
        wh = W1h + (long)c * G3H * Hd;      wl = W1l + (long)c * G3H * Hd;
        bias = b1 + (long)c * G3H;          Y = Y1 + (long)c * Bsz * G3H;
    } else {
        int c = z - Cc;
        ah = A2h + (long)c * Bsz * Hd;      al = A2l + (long)c * Bsz * Hd;
        wh = W2h + (long)c * G3H * Hd;      wl = W2l + (long)c * G3H * Hd;
        bias = b2 + (long)c * G3H;          Y = Y2 + (long)c * Bsz * G3H;
    }
    gemm_body(smem, ah + (long)b0 * 128, al + (long)b0 * 128,
              wh + (long)g0 * 128, wl + (long)g0 * 128,
              bias, Y, G3H, b0, g0);
}

// ---------------- embedding gather -> bf16 hi/lo split -----------------------
__global__ void gather_x0(const int* __restrict__ tok, const float* __restrict__ emb)
{
    long t = (long)blockIdx.x * 256 + threadIdx.x;   // B*32 threads
    int b  = (int)(t >> 5);
    int e4 = (int)(t & 31) << 2;
    float4 v = *(const float4*)(emb + (long)tok[b] * 128 + e4);
    store_split4(g_x0h, g_x0l, (long)b * 128 + e4, v);
}

// ---------------- GRU elementwise: writes bf16 split only -------------------
// l0bias != nullptr => layer 0: for cells c>0, gi is pure bias (read directly).
__global__ void gru_kernel(const float* __restrict__ hprev,
                           const float* __restrict__ l0bias)
{
    long t   = (long)blockIdx.x * 256 + threadIdx.x;
    long row = t >> 5;
    int  h4  = (int)(t & 31) << 2;
    int  c   = (int)(row >> 14);      // row / Bsz

    const float* gi;
    if (l0bias != nullptr && c > 0)
        gi = l0bias + (long)c * G3H;          // bias broadcast, no gi buffer
    else
        gi = g_gi + row * G3H;
    const float* gh = g_gh + row * G3H;

    float4 ir  = *(const float4*)(gi + h4);
    float4 iz  = *(const float4*)(gi + 128 + h4);
    float4 inn = *(const float4*)(gi + 256 + h4);
    float4 hr  = *(const float4*)(gh + h4);
    float4 hz  = *(const float4*)(gh + 128 + h4);
    float4 hnn = *(const float4*)(gh + 256 + h4);
    float4 hp  = *(const float4*)(hprev + row * 128 + h4);

    float4 out;
    {
        float r = sigf(ir.x + hr.x), z = sigf(iz.x + hz.x);
        float n = tanhf(inn.x + r * hnn.x);
        out.x = (1.0f - z) * n + z * hp.x;
    }
    {
        float r = sigf(ir.y + hr.y), z = sigf(iz.y + hz.y);
        float n = tanhf(inn.y + r * hnn.y);
        out.y = (1.0f - z) * n + z * hp.y;
    }
    {
        float r = sigf(ir.z + hr.z), z = sigf(iz.z + hz.z);
        float n = tanhf(inn.z + r * hnn.z);
        out.z = (1.0f - z) * n + z * hp.z;
    }
    {
        float r = sigf(ir.w + hr.w), z = sigf(iz.w + hz.w);
        float n = tanhf(inn.w + r * hnn.w);
        out.w = (1.0f - z) * n + z * hp.w;
    }
    store_split4(g_nh, g_nl, row * 128 + h4, out);
}

// ---------------- tiny attention over C=4 positions -> bf16 split ------------
__global__ void attn_kernel()
{
    int gw   = blockIdx.x * 4 + (threadIdx.x >> 5);
    int lane = threadIdx.x & 31;
    int b  = gw >> 2;
    int nh = gw & 3;

    float q[4], k[4], v[4];
    #pragma unroll
    for (int c = 0; c < 4; c++) {
        const float* p = g_qkv + ((long)c * Bsz + b) * G3H + nh * 32 + lane;
        q[c] = p[0];
        k[c] = p[128];
        v[c] = p[256];
    }

    float s[4][4];
    #pragma unroll
    for (int qc = 0; qc < 4; qc++) {
        #pragma unroll
        for (int kc = 0; kc < 4; kc++) {
            float p = q[qc] * k[kc];
            #pragma unroll
            for (int off = 16; off > 0; off >>= 1)
                p += __shfl_xor_sync(0xFFFFFFFFu, p, off);
            s[qc][kc] = p * 0.17677669529663687f;   // 1/sqrt(32)
        }
    }

    #pragma unroll
    for (int qc = 0; qc < 4; qc++) {
        float m = fmaxf(fmaxf(s[qc][0], s[qc][1]), fmaxf(s[qc][2], s[qc][3]));
        float e0 = expf(s[qc][0] - m), e1 = expf(s[qc][1] - m);
        float e2 = expf(s[qc][2] - m), e3 = expf(s[qc][3] - m);
        float inv = 1.0f / (e0 + e1 + e2 + e3);
        float o = (e0 * v[0] + e1 * v[1] + e2 * v[2] + e3 * v[3]) * inv;
        long off = ((long)qc * Bsz + b) * 128 + nh * 32 + lane;
        __nv_bfloat16 h = __float2bfloat16(o);
        g_aah[off] = h;
        g_aal[off] = __float2bfloat16(o - __bfloat162float(h));
    }
}

// ---------------- fused LayerNorm + gate + blend -----------------------------
// hn is reconstructed from the bf16 hi/lo split (g_nh + g_nl).
__global__ void lngate_kernel(const float* __restrict__ gg, const float* __restrict__ bb,
                              const float* __restrict__ gw, const float* __restrict__ gbp,
                              float* __restrict__ hout)
{
    int row  = blockIdx.x * 4 + (threadIdx.x >> 5);
    int lane = threadIdx.x & 31;
    const float* mp = g_msg + (long)row * 128;
    long hoff = (long)row * 128 + lane * 4;

    float4 x = *(const float4*)(mp + lane * 4);
    float s = x.x + x.y + x.z + x.w;
    #pragma unroll
    for (int off = 16; off > 0; off >>= 1) s += __shfl_xor_sync(0xFFFFFFFFu, s, off);
    float mean = s * (1.0f / 128.0f);

    float dx = x.x - mean, dy = x.y - mean, dz = x.z - mean, dw = x.w - mean;
    float sq = dx * dx + dy * dy + dz * dz + dw * dw;
    #pragma unroll
    for (int off = 16; off > 0; off >>= 1) sq += __shfl_xor_sync(0xFFFFFFFFu, sq, off);
    float rstd = rsqrtf(sq * (1.0f / 128.0f) + 1e-5f);

    float4 gv = *(const float4*)(gg + lane * 4);
    float4 bv = *(const float4*)(bb + lane * 4);
    float4 m;
    m.x = dx * rstd * gv.x + bv.x;
    m.y = dy * rstd * gv.y + bv.y;
    m.z = dz * rstd * gv.z + bv.z;
    m.w = dw * rstd * gv.w + bv.w;

    float4 hv = load_split4(g_nh, g_nl, hoff);
    float4 w1 = *(const float4*)(gw + lane * 4);
    float4 w2 = *(const float4*)(gw + 128 + lane * 4);

    float p = hv.x * w1.x + hv.y * w1.y + hv.z * w1.z + hv.w * w1.w
            + m.x * w2.x + m.y * w2.y + m.z * w2.z + m.w * w2.w;
    #pragma unroll
    for (int off = 16; off > 0; off >>= 1) p += __shfl_xor_sync(0xFFFFFFFFu, p, off);
    float gt = sigf(p + gbp[0]);

    float4 o;
    o.x = (1.0f - gt) * hv.x + gt * m.x;
    o.y = (1.0f - gt) * hv.y + gt * m.y;
    o.z = (1.0f - gt) * hv.z + gt * m.z;
    o.w = (1.0f - gt) * hv.w + gt * m.w;
    *(float4*)(hout + hoff) = o;
    store_split4(g_ph, g_pl, hoff, o);
}

// ---------------- host orchestration ----------------------------------------
extern "C" void kernel_launch(void* const* d_in, const int* in_sizes, int n_in,
                              void* d_out, int out_size)
{
    const int*   tokens     = (const int*)  d_in[0];
    const float* h_in       = (const float*)d_in[1];
    const float* emb        = (const float*)d_in[2];
    const float* wih0_c0    = (const float*)d_in[3];
    const float* bih0       = (const float*)d_in[5];
    const float* whh0       = (const float*)d_in[6];
    const float* bhh0       = (const float*)d_in[7];
    const float* wih        = (const float*)d_in[8];
    const float* whh        = (const float*)d_in[9];
    const float* bih        = (const float*)d_in[10];
    const float* bhh        = (const float*)d_in[11];
    const float* attn_in_w  = (const float*)d_in[12];
    const float* attn_in_b  = (const float*)d_in[13];
    const float* attn_out_w = (const float*)d_in[14];
    const float* attn_out_b = (const float*)d_in[15];
    const float* ln_g       = (const float*)d_in[16];
    const float* ln_b       = (const float*)d_in[17];
    const float* gate_w     = (const float*)d_in[18];
    const float* gate_b     = (const float*)d_in[19];
    const float* head_w     = (const float*)d_in[20];
    const float* head_b     = (const float*)d_in[21];

    float* yOut = (float*)d_out;                       // (B, O)
    float* hOut = yOut + (size_t)Bsz * Oo;             // (L, C, B, H)

    float *pgi, *pgh, *pqkv, *pmsg;
    cudaGetSymbolAddress((void**)&pgi,  g_gi);
    cudaGetSymbolAddress((void**)&pgh,  g_gh);
    cudaGetSymbolAddress((void**)&pqkv, g_qkv);
    cudaGetSymbolAddress((void**)&pmsg, g_msg);

    __nv_bfloat16 *x0h, *x0l, *hh, *hl, *nh, *nl, *aah, *aal, *ph, *pl;
    __nv_bfloat16 *wih0h, *wih0l, *whh0h, *whh0l, *wihh, *wihl, *whhh, *whhl;
    __nv_bfloat16 *aiwh, *aiwl, *aowh, *aowl, *hwh, *hwl;
    cudaGetSymbolAddress((void**)&x0h, g_x0h);   cudaGetSymbolAddress((void**)&x0l, g_x0l);
    cudaGetSymbolAddress((void**)&hh,  g_hh);    cudaGetSymbolAddress((void**)&hl,  g_hl);
    cudaGetSymbolAddress((void**)&nh,  g_nh);    cudaGetSymbolAddress((void**)&nl,  g_nl);
    cudaGetSymbolAddress((void**)&aah, g_aah);   cudaGetSymbolAddress((void**)&aal, g_aal);
    cudaGetSymbolAddress((void**)&ph,  g_ph);    cudaGetSymbolAddress((void**)&pl,  g_pl);
    cudaGetSymbolAddress((void**)&wih0h, g_wih0h); cudaGetSymbolAddress((void**)&wih0l, g_wih0l);
    cudaGetSymbolAddress((void**)&whh0h, g_whh0h); cudaGetSymbolAddress((void**)&whh0l, g_whh0l);
    cudaGetSymbolAddress((void**)&wihh, g_wihh); cudaGetSymbolAddress((void**)&wihl, g_wihl);
    cudaGetSymbolAddress((void**)&whhh, g_whhh); cudaGetSymbolAddress((void**)&whhl, g_whhl);
    cudaGetSymbolAddress((void**)&aiwh, g_aiwh); cudaGetSymbolAddress((void**)&aiwl, g_aiwl);
    cudaGetSymbolAddress((void**)&aowh, g_aowh); cudaGetSymbolAddress((void**)&aowl, g_aowl);
    cudaGetSymbolAddress((void**)&hwh,  g_hwh);  cudaGetSymbolAddress((void**)&hwl,  g_hwl);

    cudaFuncSetAttribute(gemm_tc,      cudaFuncAttributeMaxDynamicSharedMemorySize, SM_TOT);
    cudaFuncSetAttribute(gemm_tc_dual, cudaFuncAttributeMaxDynamicSharedMemorySize, SM_TOT);

    const long CBH = (long)Cc * Bsz * Hd;
    (void)in_sizes; (void)n_in; (void)out_size;

    // ---- prolog: split weights + h into bf16 hi/lo ----
    #define SPLIT(src, dh, dl, nelem) \
        split_pair<<<(int)((nelem) / 1024), 256>>>(src, dh, dl)
    SPLIT(wih0_c0,   wih0h, wih0l, (long)G3H * Hd);
    SPLIT(whh0,      whh0h, whh0l, (long)Cc * G3H * Hd);
    SPLIT(wih,       wihh,  wihl,  (long)(Ll-1) * Cc * G3H * Hd);
    SPLIT(whh,       whhh,  whhl,  (long)(Ll-1) * Cc * G3H * Hd);
    SPLIT(attn_in_w, aiwh,  aiwl,  (long)Ll * G3H * Hd);
    SPLIT(attn_out_w,aowh,  aowl,  (long)Ll * Hd * Hd);
    SPLIT(head_w,    hwh,   hwl,   (long)Oo * Hd);
    SPLIT(h_in,      hh,    hl,    (long)Ll * CBH);
    #undef SPLIT
    gather_x0<<<(Bsz * 32) / 256, 256>>>(tokens, emb);

    dim3 gB(Bsz / 128, G3H / 64, Cc);
    dim3 gD(Bsz / 128, G3H / 64, 2 * Cc);
    dim3 gO(Bsz / 128, Hd  / 64, Cc);

    for (int l = 0; l < Ll; l++) {
        const float* hlp = h_in + (size_t)l * CBH;

        // ---- gi + gh ----
        if (l == 0) {
            dim3 g1(Bsz / 128, G3H / 64, 1);
            gemm_tc<<<g1, 256, SM_TOT>>>(x0h, x0l, wih0h, wih0l, bih0, pgi,
                                         G3H, 0, 0, 0, 0);
            gemm_tc<<<gB, 256, SM_TOT>>>(hh, hl, whh0h, whh0l, bhh0, pgh, G3H,
                                         (long)Bsz * Hd, (long)G3H * Hd, G3H,
                                         (long)Bsz * G3H);
        } else {
            gemm_tc_dual<<<gD, 256, SM_TOT>>>(
                ph, pl,
                wihh + (size_t)(l - 1) * Cc * G3H * Hd,
                wihl + (size_t)(l - 1) * Cc * G3H * Hd,
                bih + (size_t)(l - 1) * Cc * G3H, pgi,
                hh + (size_t)l * CBH, hl + (size_t)l * CBH,
                whhh + (size_t)(l - 1) * Cc * G3H * Hd,
                whhl + (size_t)(l - 1) * Cc * G3H * Hd,
                bhh + (size_t)(l - 1) * Cc * G3H, pgh);
        }

        // ---- GRU (l=0: cells 1..3 read bias directly, no gi buffer) ----
        gru_kernel<<<((long)Cc * Bsz * 32) / 256, 256>>>(
            hlp, (l == 0) ? bih0 : nullptr);

        // ---- QKV ----
        gemm_tc<<<gB, 256, SM_TOT>>>(nh, nl,
                                     aiwh + (size_t)l * G3H * Hd,
                                     aiwl + (size_t)l * G3H * Hd,
                                     attn_in_b + (size_t)l * G3H,
                                     pqkv, G3H,
                                     (long)Bsz * Hd, 0, 0, (long)Bsz * G3H);

        // ---- attention ----
        attn_kernel<<<(Bsz * NHh) / 4, 128>>>();

        // ---- out projection ----
        gemm_tc<<<gO, 256, SM_TOT>>>(aah, aal,
                                     aowh + (size_t)l * Hd * Hd,
                                     aowl + (size_t)l * Hd * Hd,
                                     attn_out_b + (size_t)l * Hd,
                                     pmsg, Hd,
                                     (long)Bsz * Hd, 0, 0, (long)Bsz * Hd);

        // ---- fused LN + gate + blend -> hOut + g_ph/g_pl split ----
        lngate_kernel<<<(Cc * Bsz) / 4, 128>>>(ln_g + (size_t)l * Hd, ln_b + (size_t)l * Hd,
                                               gate_w + (size_t)l * 2 * Hd, gate_b + l,
                                               hOut + (size_t)l * CBH);
    }

    // ---- head: y = h_n[L-1, 0] @ head_w.T + head_b ----
    dim3 gH(Bsz / 128, Oo / 64, 1);
    gemm_tc<<<gH, 256, SM_TOT>>>(ph, pl, hwh, hwl, head_b, yOut, Oo, 0, 0, 0, 0);
}